// round 13
// baseline (speedup 1.0000x reference)
#include <cuda_runtime.h>
#include <cuda_bf16.h>
#include <cstddef>
#include <cstdint>

// Problem constants
#define NB    2
#define SLEN  2048
#define EMB   1024            // H=16, D=64
#define NBLK  256             // persistent grid (co-resident: 148 SMs x 2)
#define THR   512
#define RPB   8               // rows per 8-row chunk in P1

// Scratch (__device__ globals; no allocation).
// g_sv: atomic accumulator; zeroed by each block's slice at launch end.
// g_cnt self-resets; g_flag toggles (sense-reversing) -> replay-safe.
__device__ float g_sv[NB][EMB];
__device__ float g_y[NB][EMB];
__device__ int   g_cnt[2];
__device__ volatile int g_flag[2];

// ---- cp.async helpers ------------------------------------------------------
__device__ __forceinline__ void cp_async16(uint32_t saddr, const void* gaddr) {
    asm volatile("cp.async.cg.shared.global [%0], [%1], 16;"
                 :: "r"(saddr), "l"(gaddr) : "memory");
}
__device__ __forceinline__ void cp_async_commit() {
    asm volatile("cp.async.commit_group;" ::: "memory");
}
__device__ __forceinline__ void cp_async_wait0() {
    asm volatile("cp.async.wait_group 0;" ::: "memory");
}

// Sense-reversing grid barrier: counter self-resets, flag toggles.
// Waiters compare against the flag value read BEFORE arriving (parity-free).
__device__ __forceinline__ void gbar(int k)
{
    __syncthreads();
    if (threadIdx.x == 0) {
        const int old = g_flag[k];
        __threadfence();                       // publish writes (incl. REDG)
        if (atomicAdd(&g_cnt[k], 1) == NBLK - 1) {
            g_cnt[k] = 0;                      // self-reset (all have arrived)
            __threadfence();
            g_flag[k] = old ^ 1;               // release
        } else {
            while (g_flag[k] == old) {}
        }
        __threadfence();                       // acquire
    }
    __syncthreads();
}

__global__ void __launch_bounds__(THR, 2)
k_fused(const float* __restrict__ vals,
        const float* __restrict__ Wv,
        const float* __restrict__ Wo,
        const float* __restrict__ bo,
        float*       __restrict__ out)
{
    const int b   = blockIdx.x;
    const int tid = threadIdx.x;

    __shared__ __align__(16) float4 s_wo[1024];   // 16 KB: 4 Wo rows
    __shared__ __align__(16) float4 s_sv[512];    //  8 KB: sv (both batches)
    __shared__ __align__(16) float4 s_t[512];     //  8 KB: t  (both batches)
    __shared__ float s_part3[NB][4][4];

    const uint32_t swo = (uint32_t)__cvta_generic_to_shared(s_wo);

    // ======================= P1: column sums -> REDG =======================
    // Block b: batch n = b>>7, chunks 2*(b&127)+{0,1}; each half-block sums
    // one 8-row chunk; halves combined in smem; 4 REDG floats per thread<256.
    {
        const int n   = b >> 7;
        const int c   = ((b & 127) << 1) + (tid >> 8);
        const int col = tid & 255;
        const float4* __restrict__ base =
            (const float4*)(vals + (size_t)n * SLEN * EMB + (size_t)c * RPB * EMB);

        float4 acc = make_float4(0.f, 0.f, 0.f, 0.f);
        #pragma unroll
        for (int s = 0; s < RPB; ++s) {
            float4 v = __ldg(&base[s * (EMB / 4) + col]);
            acc.x += v.x; acc.y += v.y; acc.z += v.z; acc.w += v.w;
        }
        s_t[tid] = acc;                     // scratch use
        __syncthreads();
        if (tid < 256) {
            float4 a = s_t[tid];
            const float4 c2 = s_t[256 + tid];
            a.x += c2.x; a.y += c2.y; a.z += c2.z; a.w += c2.w;
            float* dst = &g_sv[n][tid * 4];
            atomicAdd(dst + 0, a.x);        // RED.ADD (no return)
            atomicAdd(dst + 1, a.y);
            atomicAdd(dst + 2, a.z);
            atomicAdd(dst + 3, a.w);
        }
    }

    // prefetch this block's 4 Wo rows (16 KB) - overlaps bar1 wait
    {
        const float4* __restrict__ wsrc = (const float4*)(Wo + (size_t)b * 4 * EMB);
        cp_async16(swo + (uint32_t)tid * 16,         wsrc + tid);
        cp_async16(swo + (uint32_t)(tid + 512) * 16, wsrc + tid + 512);
        cp_async_commit();
    }

    gbar(0);   // all column sums complete

    // ============ local stage: sv -> t (full, both batches) -> y chunk ======
    // Load sv into smem (8 KB), every block computes the FULL t locally
    // (128K FMA), then its own 4-element y chunk for both batches.
    s_sv[tid] = __ldcg(&((const float4*)g_sv)[tid]);
    __syncthreads();
    {
        // thread -> t[n][e0..e0+3]:  n = tid>>8, e0 = (tid&255)*4
        const int n  = tid >> 8;
        const int e0 = (tid & 255) * 4;
        const int h  = e0 >> 6;
        const int d0 = e0 & 63;
        const float* __restrict__ svh = (const float*)s_sv + n * EMB + (h << 6);

        float a0 = 0.f, a1 = 0.f, a2 = 0.f, a3 = 0.f;
        #pragma unroll 16
        for (int dp = 0; dp < 64; ++dp) {
            const float s = svh[dp];
            a0 += __ldg(&Wv[(d0 + 0) * 64 + dp]) * s;
            a1 += __ldg(&Wv[(d0 + 1) * 64 + dp]) * s;
            a2 += __ldg(&Wv[(d0 + 2) * 64 + dp]) * s;
            a3 += __ldg(&Wv[(d0 + 3) * 64 + dp]) * s;
        }
        s_t[tid] = make_float4(a0, a1, a2, a3);   // t[2][1024] as float4[512]
    }
    cp_async_wait0();                              // Wo rows resident
    __syncthreads();

    // y[4b..4b+4) for both batches: 16 warps, 4 per e (quarter-split), from smem
    {
        const int e0   = b * 4;
        const int w    = tid >> 5;
        const int lane = tid & 31;
        const int el   = w >> 2;         // e-local 0..3
        const int q    = w & 3;          // quarter (64 float4 each)

        const float4* __restrict__ worow = s_wo + el * 256 + q * 64;
        const float4* __restrict__ t0 = s_t + q * 64;          // batch 0
        const float4* __restrict__ t1 = s_t + 256 + q * 64;    // batch 1

        float a0 = 0.f, a1 = 0.f;
        #pragma unroll
        for (int i = lane; i < 64; i += 32) {
            const float4 wv = worow[i];
            const float4 x  = t0[i];
            const float4 z  = t1[i];
            a0 += wv.x * x.x + wv.y * x.y + wv.z * x.z + wv.w * x.w;
            a1 += wv.x * z.x + wv.y * z.y + wv.z * z.z + wv.w * z.w;
        }
        #pragma unroll
        for (int o = 16; o; o >>= 1) {
            a0 += __shfl_xor_sync(0xFFFFFFFFu, a0, o);
            a1 += __shfl_xor_sync(0xFFFFFFFFu, a1, o);
        }
        if (lane == 0) {
            s_part3[0][el][q] = a0;
            s_part3[1][el][q] = a1;
        }
        __syncthreads();
        if (tid < 8) {                    // n = tid>>2, e-local = tid&3
            const int nn = tid >> 2;
            const int ee = tid & 3;
            g_y[nn][e0 + ee] = ((s_part3[nn][ee][0] + s_part3[nn][ee][1])
                              + (s_part3[nn][ee][2] + s_part3[nn][ee][3]))
                             + __ldg(&bo[e0 + ee]);
        }
    }

    gbar(1);   // full y visible everywhere

    // ===================== P4: broadcast y to all rows =====================
    // Block b: batch n = b>>7, 16-row slab; halves write 8 rows each.
    {
        const int n    = b >> 7;
        const int c    = b & 127;
        const int half = tid >> 8;
        const int col  = tid & 255;
        const float4 v = __ldcg(&((const float4*)g_y[n])[col]);

        float4* __restrict__ dst =
            (float4*)(out + (size_t)n * SLEN * EMB
                          + ((size_t)c * 16 + half * 8) * EMB);
        #pragma unroll
        for (int s = 0; s < 8; ++s)
            __stcs(&dst[s * (EMB / 4) + col], v);
    }

    // zero this block's g_sv slice for the next replay (after bar2 -> all
    // reads done; kernel boundary orders it before the next launch).
    if (tid < 8) ((float*)g_sv)[b * 8 + tid] = 0.f;
}

// ---------------------------------------------------------------------------
// Inputs (metadata order): 0=values 1=keys 2=queries 3=mask 4=Wv 5=Wk 6=Wq
//                          7=Wo 8=bo.   Output: float32 [2, 2048, 1024].
// ---------------------------------------------------------------------------
extern "C" void kernel_launch(void* const* d_in, const int* in_sizes, int n_in,
                              void* d_out, int out_size)
{
    const float* values = (const float*)d_in[0];
    const float* Wv     = (const float*)d_in[4];
    const float* Wo     = (const float*)d_in[7];
    const float* bo     = (const float*)d_in[8];
    float*       out    = (float*)d_out;

    k_fused<<<NBLK, THR>>>(values, Wv, Wo, bo, out);
}

// round 14
// speedup vs baseline: 4.4229x; 4.4229x over previous
#include <cuda_runtime.h>
#include <cuda_bf16.h>
#include <cstddef>
#include <cstdint>

// Problem constants
#define NB    2
#define SLEN  2048
#define EMB   1024            // H=16, D=64
#define NBLK  256             // persistent grid (co-resident: 148 SMs x 2)
#define THR   512
#define CPN   256             // partial chunks per batch (8 rows each)

// Scratch (__device__ globals; no allocation). Zero-init counters/flags;
// the last exiting block resets them -> graph-replay safe.
__device__ __align__(32) float g_part[NB][CPN][EMB];  // partials (2 MB)
__device__ __align__(32) float g_t[NB][EMB];
__device__ __align__(32) float g_y[NB][EMB];
__device__ int   g_c1, g_c2, g_c3, g_ce;
__device__ volatile int g_f1, g_f2, g_f3;

// ---- 256-bit vector memory ops (Blackwell) --------------------------------
__device__ __forceinline__ void ldg8_nc(const float* g, float4& a, float4& b) {
    asm volatile("ld.global.nc.v8.f32 {%0,%1,%2,%3,%4,%5,%6,%7}, [%8];"
                 : "=f"(a.x), "=f"(a.y), "=f"(a.z), "=f"(a.w),
                   "=f"(b.x), "=f"(b.y), "=f"(b.z), "=f"(b.w)
                 : "l"(g));
}
__device__ __forceinline__ void ldg8(const float* g, float4& a, float4& b) {
    asm volatile("ld.global.v8.f32 {%0,%1,%2,%3,%4,%5,%6,%7}, [%8];"
                 : "=f"(a.x), "=f"(a.y), "=f"(a.z), "=f"(a.w),
                   "=f"(b.x), "=f"(b.y), "=f"(b.z), "=f"(b.w)
                 : "l"(g));
}
__device__ __forceinline__ void stg8_cs(float* g, const float4& a, const float4& b) {
    asm volatile("st.global.cs.v8.f32 [%0], {%1,%2,%3,%4,%5,%6,%7,%8};"
                 :: "l"(g), "f"(a.x), "f"(a.y), "f"(a.z), "f"(a.w),
                    "f"(b.x), "f"(b.y), "f"(b.z), "f"(b.w) : "memory");
}

// ---- cp.async helpers ------------------------------------------------------
__device__ __forceinline__ void cp_async16(uint32_t saddr, const void* gaddr) {
    asm volatile("cp.async.cg.shared.global [%0], [%1], 16;"
                 :: "r"(saddr), "l"(gaddr) : "memory");
}
__device__ __forceinline__ void cp_async_commit() {
    asm volatile("cp.async.commit_group;" ::: "memory");
}
__device__ __forceinline__ void cp_async_wait0() {
    asm volatile("cp.async.wait_group 0;" ::: "memory");
}

__global__ void __launch_bounds__(THR, 2)
k_fused(const float* __restrict__ vals,
        const float* __restrict__ Wv,
        const float* __restrict__ Wo,
        const float* __restrict__ bo,
        float*       __restrict__ out)
{
    const int b   = blockIdx.x;
    const int tid = threadIdx.x;

    __shared__ __align__(32) float4 s_wo[1024];   // 16 KB: 4 Wo rows
    __shared__ __align__(32) float4 s_a[512];     //  8 KB: P1 combine (lo)
    __shared__ __align__(32) float4 s_b[512];     //  8 KB: P1 combine (hi)
    __shared__ float s_part3[NB][4][4];

    const uint32_t swo = (uint32_t)__cvta_generic_to_shared(s_wo);

    // ======================= P1: column-sum partials =======================
    // Block b: batch n = b>>7, chunks c0,c0+1 (8 rows each). 512 threads =
    // (chunk, rowhalf, lane8): each thread sums 4 rows with LDG.256;
    // rowhalves combined in smem; 256 threads write float8 partials.
    {
        const int n     = b >> 7;
        const int c0    = (b & 127) << 1;
        const int sub   = tid >> 7;        // 0..3
        const int lane8 = tid & 127;       // float8 column
        const int chunk = sub >> 1;        // 0..1
        const int rh    = sub & 1;         // row half (4 rows each)

        const float* __restrict__ base =
            vals + ((size_t)n * SLEN + (size_t)(c0 + chunk) * 8 + rh * 4) * EMB
                 + lane8 * 8;

        float4 aA = make_float4(0.f, 0.f, 0.f, 0.f);
        float4 aB = make_float4(0.f, 0.f, 0.f, 0.f);
        #pragma unroll
        for (int s = 0; s < 4; ++s) {
            float4 vA, vB;
            ldg8_nc(base + s * EMB, vA, vB);
            aA.x += vA.x; aA.y += vA.y; aA.z += vA.z; aA.w += vA.w;
            aB.x += vB.x; aB.y += vB.y; aB.z += vB.z; aB.w += vB.w;
        }
        s_a[tid] = aA; s_b[tid] = aB;
        __syncthreads();
        if (rh == 0) {                     // tid in [0,128) u [256,384)
            const float4 cA = s_a[tid + 128], cB = s_b[tid + 128];
            aA.x += cA.x; aA.y += cA.y; aA.z += cA.z; aA.w += cA.w;
            aB.x += cB.x; aB.y += cB.y; aB.z += cB.z; aB.w += cB.w;
            float4* dst = (float4*)&g_part[n][c0 + chunk][lane8 * 8];
            dst[0] = aA; dst[1] = aB;
        }
    }

    // ---- bar1 arrive (non-blocking) + Wo prefetch overlapped with waits ----
    __syncthreads();
    {
        const float4* __restrict__ wsrc = (const float4*)(Wo + (size_t)b * 4 * EMB);
        cp_async16(swo + (uint32_t)tid * 16,         wsrc + tid);
        cp_async16(swo + (uint32_t)(tid + 512) * 16, wsrc + tid + 512);
        cp_async_commit();
    }
    if (tid == 0) {
        __threadfence();
        if (atomicAdd(&g_c1, 1) == NBLK - 1) g_f1 = 1;
    }

    // ================= P2 (32 blocks): partials -> sv -> t =================
    if (b < 32) {
        if (tid == 0) {
            while (g_f1 == 0) {}
            __threadfence();
        }
        __syncthreads();

        const int n  = b >> 4;
        const int h  = b & 15;
        const int L  = tid & 15;       // float4 col within the head
        const int cs = tid >> 4;       // 0..31 c-split (8 chunks each)

        float4 p = make_float4(0.f, 0.f, 0.f, 0.f);
        #pragma unroll
        for (int k = 0; k < 8; ++k) {
            const int c = cs * 8 + k;
            float4 v = __ldcg(&((const float4*)g_part[n][c])[h * 16 + L]);
            p.x += v.x; p.y += v.y; p.z += v.z; p.w += v.w;
        }
        s_a[cs * 16 + L] = p;
        __syncthreads();
        #pragma unroll
        for (int st = 16; st >= 1; st >>= 1) {
            if (cs < st) {
                float4 a = s_a[cs * 16 + L], d2 = s_a[(cs + st) * 16 + L];
                a.x += d2.x; a.y += d2.y; a.z += d2.z; a.w += d2.w;
                s_a[cs * 16 + L] = a;
            }
            __syncthreads();
        }
        if (tid < 64) {
            const float* __restrict__ svh  = (const float*)s_a;    // 64 floats
            const float* __restrict__ wrow = Wv + tid * 64;
            float acc = 0.f;
            #pragma unroll 16
            for (int dp = 0; dp < 64; ++dp) acc += __ldg(&wrow[dp]) * svh[dp];
            g_t[n][h * 64 + tid] = acc;
        }
        __syncthreads();
        if (tid == 0) {
            __threadfence();
            if (atomicAdd(&g_c2, 1) == 31) g_f2 = 1;
        }
    }

    // ---------------- all blocks: wait for t, Wo now in smem ----------------
    if (tid == 0) {
        while (g_f2 == 0) {}
        __threadfence();
    }
    __syncthreads();
    cp_async_wait0();
    __syncthreads();

    // ===== P3: y[4b..4b+4) = s_wo @ t + bo (both batches), Wo from SMEM =====
    {
        const int e0   = b * 4;
        const int w    = tid >> 5;       // warp 0..15
        const int lane = tid & 31;
        const int el   = w >> 2;         // e-local 0..3
        const int q    = w & 3;          // quarter (64 float4 each)

        const float4* __restrict__ worow = s_wo + el * 256 + q * 64;
        const float4* __restrict__ t0 = (const float4*)g_t[0] + q * 64;
        const float4* __restrict__ t1 = (const float4*)g_t[1] + q * 64;

        float a0 = 0.f, a1 = 0.f;
        #pragma unroll
        for (int i = lane; i < 64; i += 32) {
            float4 wv = worow[i];
            float4 x  = __ldcg(&t0[i]);
            float4 z  = __ldcg(&t1[i]);
            a0 += wv.x * x.x + wv.y * x.y + wv.z * x.z + wv.w * x.w;
            a1 += wv.x * z.x + wv.y * z.y + wv.z * z.z + wv.w * z.w;
        }
        #pragma unroll
        for (int o = 16; o; o >>= 1) {
            a0 += __shfl_xor_sync(0xFFFFFFFFu, a0, o);
            a1 += __shfl_xor_sync(0xFFFFFFFFu, a1, o);
        }
        if (lane == 0) {
            s_part3[0][el][q] = a0;
            s_part3[1][el][q] = a1;
        }
        __syncthreads();
        if (tid < 8) {                    // n = tid>>2, e-local = tid&3
            const int nn = tid >> 2;
            const int ee = tid & 3;
            g_y[nn][e0 + ee] = ((s_part3[nn][ee][0] + s_part3[nn][ee][1])
                              + (s_part3[nn][ee][2] + s_part3[nn][ee][3]))
                             + __ldg(&bo[e0 + ee]);
        }
    }

    // ------------------------------ bar3 -----------------------------------
    __syncthreads();
    if (tid == 0) {
        __threadfence();
        if (atomicAdd(&g_c3, 1) == NBLK - 1) {
            g_f3 = 1;
        } else {
            while (g_f3 == 0) {}
        }
        __threadfence();
    }
    __syncthreads();

    // ===================== P4: broadcast y to all rows =====================
    // Block b: batch n = b>>7, 16-row slab. (rowgroup rg, lane8): thread
    // stores 4 rows with STG.256 (evict-first; output never re-read).
    {
        const int n     = b >> 7;
        const int c     = b & 127;
        const int lane8 = tid & 127;
        const int rg    = tid >> 7;      // 0..3

        float4 yA, yB;
        ldg8(&g_y[n][lane8 * 8], yA, yB);

        float* __restrict__ dst =
            out + ((size_t)n * SLEN + (size_t)c * 16 + rg * 4) * EMB + lane8 * 8;
        #pragma unroll
        for (int s = 0; s < 4; ++s)
            stg8_cs(dst + s * EMB, yA, yB);
    }

    // ======================= exit: reset for replay ========================
    __threadfence();
    __syncthreads();
    if (tid == 0) {
        if (atomicAdd(&g_ce, 1) == NBLK - 1) {
            g_c1 = 0; g_c2 = 0; g_c3 = 0; g_ce = 0;
            g_f1 = 0; g_f2 = 0; g_f3 = 0;
        }
    }
}

// ---------------------------------------------------------------------------
// Inputs (metadata order): 0=values 1=keys 2=queries 3=mask 4=Wv 5=Wk 6=Wq
//                          7=Wo 8=bo.   Output: float32 [2, 2048, 1024].
// ---------------------------------------------------------------------------
extern "C" void kernel_launch(void* const* d_in, const int* in_sizes, int n_in,
                              void* d_out, int out_size)
{
    const float* values = (const float*)d_in[0];
    const float* Wv     = (const float*)d_in[4];
    const float* Wo     = (const float*)d_in[7];
    const float* bo     = (const float*)d_in[8];
    float*       out    = (float*)d_out;

    k_fused<<<NBLK, THR>>>(values, Wv, Wo, bo, out);
}